// round 14
// baseline (speedup 1.0000x reference)
#include <cuda_runtime.h>
#include <cuda_bf16.h>

// LightGCNConv R14: R13 (measured best 47.6us) with ONE knob: bin kernel
// block size 256 -> 512 (deeper per-SM warp pool to hide the 318-cyc
// returning-atomic latency). All kernel bodies byte-identical to R13.
//
// Pipeline (4 launches, no memset):
//  1) zero: outdeg/cursor/ovf_count = 0 (int4 stores)
//  2) bin: one edge/thread; outdeg RED; slot=atomicAdd(cursor[dst]);
//     bucket[dst*CAP+slot]=src; overflow (deg>CAP, ~never) -> pair list
//  3) norm: 4 nodes/thread, vectorized rsqrt of clipped degrees
//  4) gather: 16 lanes/node, float4, unroll 4, one write per output element

#define MAX_NODES 100000   // divisible by 4
#define DFEAT 64
#define DVEC 16   // float4s per row
#define CAP 32    // bucket row = 128B line; P(deg>32) ~ 4e-9
#define OVF_MAX 4096

__device__ int   g_outdeg[MAX_NODES];
__device__ int   g_cursor[MAX_NODES];          // becomes in-degree
__device__ float g_nsrc[MAX_NODES];
__device__ float g_ndst[MAX_NODES];
__device__ int   g_bucket[MAX_NODES * CAP];    // 12.8 MB scratch
__device__ int   g_ovf_src[OVF_MAX];
__device__ int   g_ovf_dst[OVF_MAX];
__device__ int   g_ovf_count;

// One thread zeroes 4 outdeg + 4 cursor entries (int4 stores).
__global__ void zero_kernel(int n4) {
    int i = blockIdx.x * blockDim.x + threadIdx.x;
    if (i < n4) {
        ((int4*)g_outdeg)[i] = make_int4(0, 0, 0, 0);
        ((int4*)g_cursor)[i] = make_int4(0, 0, 0, 0);
    }
    if (i == 0) g_ovf_count = 0;
}

// VERBATIM R7/R13 body.
__global__ void bin_kernel(const int* __restrict__ src,
                           const int* __restrict__ dst, int E) {
    int e = blockIdx.x * blockDim.x + threadIdx.x;
    if (e >= E) return;
    int s = src[e];
    int d = dst[e];
    atomicAdd(&g_outdeg[s], 1);                // result unused -> RED
    int slot = atomicAdd(&g_cursor[d], 1);
    if (slot < CAP) {
        g_bucket[d * CAP + slot] = s;
    } else {
        int pos = atomicAdd(&g_ovf_count, 1);
        if (pos < OVF_MAX) {
            g_ovf_src[pos] = s;
            g_ovf_dst[pos] = d;
        }
    }
}

// One thread computes 4 nodes' norms (vectorized int4 loads, float4 stores).
__global__ void norm_kernel(int n4) {
    int i = blockIdx.x * blockDim.x + threadIdx.x;
    if (i >= n4) return;
    int4 od = ((const int4*)g_outdeg)[i];
    int4 id = ((const int4*)g_cursor)[i];
    float4 ns, nd;
    ns.x = rsqrtf((float)max(od.x, 1));
    ns.y = rsqrtf((float)max(od.y, 1));
    ns.z = rsqrtf((float)max(od.z, 1));
    ns.w = rsqrtf((float)max(od.w, 1));
    nd.x = rsqrtf((float)max(id.x, 1));
    nd.y = rsqrtf((float)max(id.y, 1));
    nd.z = rsqrtf((float)max(id.z, 1));
    nd.w = rsqrtf((float)max(id.w, 1));
    ((float4*)g_nsrc)[i] = ns;
    ((float4*)g_ndst)[i] = nd;
}

// VERBATIM R7/R13: 16 lanes per node; lane q owns float4 #q.
__global__ void gather_kernel(const float4* __restrict__ feat,
                              float4* __restrict__ out, int N) {
    int t = blockIdx.x * blockDim.x + threadIdx.x;
    int node = t >> 4;
    int q = t & 15;
    if (node >= N) return;

    int deg = __ldg(&g_cursor[node]);          // broadcast across the 16 lanes
    int k = min(deg, CAP);

    float4 acc = make_float4(0.f, 0.f, 0.f, 0.f);
    const int* bkt = &g_bucket[node * CAP];

    #pragma unroll 4
    for (int i = 0; i < k; i++) {
        int s = __ldg(&bkt[i]);                // broadcast (single line per node)
        float rn = __ldg(&g_nsrc[s]);          // broadcast
        float4 v = __ldg(&feat[(long long)s * DVEC + q]);
        acc.x = fmaf(v.x, rn, acc.x);
        acc.y = fmaf(v.y, rn, acc.y);
        acc.z = fmaf(v.z, rn, acc.z);
        acc.w = fmaf(v.w, rn, acc.w);
    }

    // Slow path: edges that overflowed this node's bucket (expected: none).
    if (deg > CAP) {
        int ovfn = min(g_ovf_count, OVF_MAX);
        for (int j = 0; j < ovfn; j++) {
            if (g_ovf_dst[j] == node) {
                int s = g_ovf_src[j];
                float rn = __ldg(&g_nsrc[s]);
                float4 v = __ldg(&feat[(long long)s * DVEC + q]);
                acc.x = fmaf(v.x, rn, acc.x);
                acc.y = fmaf(v.y, rn, acc.y);
                acc.z = fmaf(v.z, rn, acc.z);
                acc.w = fmaf(v.w, rn, acc.w);
            }
        }
    }

    float nd = __ldg(&g_ndst[node]);
    acc.x *= nd; acc.y *= nd; acc.z *= nd; acc.w *= nd;
    out[(long long)node * DVEC + q] = acc;
}

extern "C" void kernel_launch(void* const* d_in, const int* in_sizes, int n_in,
                              void* d_out, int out_size) {
    const float4* feat = (const float4*)d_in[0];
    const int*    src  = (const int*)d_in[1];
    const int*    dst  = (const int*)d_in[2];
    float4*       out  = (float4*)d_out;

    int N = in_sizes[0] / DFEAT;   // 100000
    int E = in_sizes[1];           // 1000000
    int N4 = (N + 3) / 4;          // 25000

    // 1) zero scratch (vectorized)
    {
        int threads = 256;
        int blocks = (N4 + threads - 1) / threads;
        zero_kernel<<<blocks, threads>>>(N4);
    }

    // 2) degree count + dst binning (512-thread blocks; body verbatim)
    {
        int threads = 512;
        int blocks = (E + threads - 1) / threads;
        bin_kernel<<<blocks, threads>>>(src, dst, E);
    }

    // 3) per-node norms (vectorized, 4 nodes/thread)
    {
        int threads = 256;
        int blocks = (N4 + threads - 1) / threads;
        norm_kernel<<<blocks, threads>>>(N4);
    }

    // 4) register-accumulated gather, single write per output element (verbatim)
    {
        long long total = (long long)N * DVEC;
        int threads = 256;
        int blocks = (int)((total + threads - 1) / threads);
        gather_kernel<<<blocks, threads>>>(feat, out, N);
    }
}

// round 15
// speedup vs baseline: 1.0261x; 1.0261x over previous
#include <cuda_runtime.h>
#include <cuda_bf16.h>

// LightGCNConv R15: R13 kernel bodies (measured best 47.6us) + PDL
// (programmatic dependent launch) on bin/norm/gather to overlap the ~4us of
// inter-kernel launch gaps. Each dependent kernel runs its independent
// prologue early and calls cudaGridDependencySynchronize() before touching
// predecessor-written state.
//
// Pipeline (4 launches, PDL-chained):
//  1) zero: outdeg/cursor/ovf_count = 0 (int4 stores)
//  2) bin: one edge/thread; loads src/dst early; sync; atomics+bucket store
//  3) norm: sync; 4 nodes/thread vectorized rsqrt
//  4) gather: sync; 16 lanes/node, float4, unroll 4, one write per element

#define MAX_NODES 100000   // divisible by 4
#define DFEAT 64
#define DVEC 16   // float4s per row
#define CAP 32    // bucket row = 128B line; P(deg>32) ~ 4e-9
#define OVF_MAX 4096

__device__ int   g_outdeg[MAX_NODES];
__device__ int   g_cursor[MAX_NODES];          // becomes in-degree
__device__ float g_nsrc[MAX_NODES];
__device__ float g_ndst[MAX_NODES];
__device__ int   g_bucket[MAX_NODES * CAP];    // 12.8 MB scratch
__device__ int   g_ovf_src[OVF_MAX];
__device__ int   g_ovf_dst[OVF_MAX];
__device__ int   g_ovf_count;

// One thread zeroes 4 outdeg + 4 cursor entries (int4 stores).
__global__ void zero_kernel(int n4) {
    int i = blockIdx.x * blockDim.x + threadIdx.x;
    if (i < n4) {
        ((int4*)g_outdeg)[i] = make_int4(0, 0, 0, 0);
        ((int4*)g_cursor)[i] = make_int4(0, 0, 0, 0);
    }
    if (i == 0) g_ovf_count = 0;
}

// Body verbatim R13; src/dst loads issued before the PDL dependency sync.
__global__ void bin_kernel(const int* __restrict__ src,
                           const int* __restrict__ dst, int E) {
    int e = blockIdx.x * blockDim.x + threadIdx.x;
    if (e >= E) {
        cudaGridDependencySynchronize();
        return;
    }
    int s = src[e];                            // independent of zero_kernel
    int d = dst[e];
    cudaGridDependencySynchronize();           // wait: zero_kernel complete
    atomicAdd(&g_outdeg[s], 1);                // result unused -> RED
    int slot = atomicAdd(&g_cursor[d], 1);
    if (slot < CAP) {
        g_bucket[d * CAP + slot] = s;
    } else {
        int pos = atomicAdd(&g_ovf_count, 1);
        if (pos < OVF_MAX) {
            g_ovf_src[pos] = s;
            g_ovf_dst[pos] = d;
        }
    }
}

// One thread computes 4 nodes' norms (vectorized int4 loads, float4 stores).
__global__ void norm_kernel(int n4) {
    int i = blockIdx.x * blockDim.x + threadIdx.x;
    cudaGridDependencySynchronize();           // wait: bin_kernel complete
    if (i >= n4) return;
    int4 od = ((const int4*)g_outdeg)[i];
    int4 id = ((const int4*)g_cursor)[i];
    float4 ns, nd;
    ns.x = rsqrtf((float)max(od.x, 1));
    ns.y = rsqrtf((float)max(od.y, 1));
    ns.z = rsqrtf((float)max(od.z, 1));
    ns.w = rsqrtf((float)max(od.w, 1));
    nd.x = rsqrtf((float)max(id.x, 1));
    nd.y = rsqrtf((float)max(id.y, 1));
    nd.z = rsqrtf((float)max(id.z, 1));
    nd.w = rsqrtf((float)max(id.w, 1));
    ((float4*)g_nsrc)[i] = ns;
    ((float4*)g_ndst)[i] = nd;
}

// Body verbatim R13: 16 lanes per node; lane q owns float4 #q.
__global__ void gather_kernel(const float4* __restrict__ feat,
                              float4* __restrict__ out, int N) {
    int t = blockIdx.x * blockDim.x + threadIdx.x;
    int node = t >> 4;
    int q = t & 15;
    cudaGridDependencySynchronize();           // wait: norm_kernel complete
    if (node >= N) return;

    int deg = __ldg(&g_cursor[node]);          // broadcast across the 16 lanes
    int k = min(deg, CAP);

    float4 acc = make_float4(0.f, 0.f, 0.f, 0.f);
    const int* bkt = &g_bucket[node * CAP];

    #pragma unroll 4
    for (int i = 0; i < k; i++) {
        int s = __ldg(&bkt[i]);                // broadcast (single line per node)
        float rn = __ldg(&g_nsrc[s]);          // broadcast
        float4 v = __ldg(&feat[(long long)s * DVEC + q]);
        acc.x = fmaf(v.x, rn, acc.x);
        acc.y = fmaf(v.y, rn, acc.y);
        acc.z = fmaf(v.z, rn, acc.z);
        acc.w = fmaf(v.w, rn, acc.w);
    }

    // Slow path: edges that overflowed this node's bucket (expected: none).
    if (deg > CAP) {
        int ovfn = min(g_ovf_count, OVF_MAX);
        for (int j = 0; j < ovfn; j++) {
            if (g_ovf_dst[j] == node) {
                int s = g_ovf_src[j];
                float rn = __ldg(&g_nsrc[s]);
                float4 v = __ldg(&feat[(long long)s * DVEC + q]);
                acc.x = fmaf(v.x, rn, acc.x);
                acc.y = fmaf(v.y, rn, acc.y);
                acc.z = fmaf(v.z, rn, acc.z);
                acc.w = fmaf(v.w, rn, acc.w);
            }
        }
    }

    float nd = __ldg(&g_ndst[node]);
    acc.x *= nd; acc.y *= nd; acc.z *= nd; acc.w *= nd;
    out[(long long)node * DVEC + q] = acc;
}

static inline void launch_pdl(void* func, dim3 grid, dim3 block,
                              void** args) {
    cudaLaunchConfig_t cfg;
    memset(&cfg, 0, sizeof(cfg));
    cudaLaunchAttribute attr[1];
    attr[0].id = cudaLaunchAttributeProgrammaticStreamSerialization;
    attr[0].val.programmaticStreamSerializationAllowed = 1;
    cfg.gridDim = grid;
    cfg.blockDim = block;
    cfg.dynamicSmemBytes = 0;
    cfg.stream = 0;
    cfg.attrs = attr;
    cfg.numAttrs = 1;
    cudaLaunchKernelExC(&cfg, func, args);
}

extern "C" void kernel_launch(void* const* d_in, const int* in_sizes, int n_in,
                              void* d_out, int out_size) {
    const float4* feat = (const float4*)d_in[0];
    const int*    src  = (const int*)d_in[1];
    const int*    dst  = (const int*)d_in[2];
    float4*       out  = (float4*)d_out;

    int N = in_sizes[0] / DFEAT;   // 100000
    int E = in_sizes[1];           // 1000000
    int N4 = (N + 3) / 4;          // 25000

    // 1) zero scratch (vectorized) — plain launch, head of the chain
    {
        int threads = 256;
        int blocks = (N4 + threads - 1) / threads;
        zero_kernel<<<blocks, threads>>>(N4);
    }

    // 2) degree count + dst binning — PDL on zero
    {
        int threads = 256;
        int blocks = (E + threads - 1) / threads;
        void* args[] = {(void*)&src, (void*)&dst, (void*)&E};
        launch_pdl((void*)bin_kernel, dim3(blocks), dim3(threads), args);
    }

    // 3) per-node norms — PDL on bin
    {
        int threads = 256;
        int blocks = (N4 + threads - 1) / threads;
        void* args[] = {(void*)&N4};
        launch_pdl((void*)norm_kernel, dim3(blocks), dim3(threads), args);
    }

    // 4) register-accumulated gather — PDL on norm
    {
        long long total = (long long)N * DVEC;
        int threads = 256;
        int blocks = (int)((total + threads - 1) / threads);
        void* args[] = {(void*)&feat, (void*)&out, (void*)&N};
        launch_pdl((void*)gather_kernel, dim3(blocks), dim3(threads), args);
    }
}

// round 16
// speedup vs baseline: 1.0565x; 1.0297x over previous
#include <cuda_runtime.h>
#include <cuda_bf16.h>

// LightGCNConv R16: R15 (measured best 46.7us: PDL-chained zero/bin/norm/
// gather) with ONE knob: gather block 256 -> 128 (finer scheduling granularity
// during the PDL overlap window, less per-block tail quantization).
// All kernel bodies byte-identical to R15.

#define MAX_NODES 100000   // divisible by 4
#define DFEAT 64
#define DVEC 16   // float4s per row
#define CAP 32    // bucket row = 128B line; P(deg>32) ~ 4e-9
#define OVF_MAX 4096

__device__ int   g_outdeg[MAX_NODES];
__device__ int   g_cursor[MAX_NODES];          // becomes in-degree
__device__ float g_nsrc[MAX_NODES];
__device__ float g_ndst[MAX_NODES];
__device__ int   g_bucket[MAX_NODES * CAP];    // 12.8 MB scratch
__device__ int   g_ovf_src[OVF_MAX];
__device__ int   g_ovf_dst[OVF_MAX];
__device__ int   g_ovf_count;

// One thread zeroes 4 outdeg + 4 cursor entries (int4 stores).
__global__ void zero_kernel(int n4) {
    int i = blockIdx.x * blockDim.x + threadIdx.x;
    if (i < n4) {
        ((int4*)g_outdeg)[i] = make_int4(0, 0, 0, 0);
        ((int4*)g_cursor)[i] = make_int4(0, 0, 0, 0);
    }
    if (i == 0) g_ovf_count = 0;
}

// Body verbatim; src/dst loads issued before the PDL dependency sync.
__global__ void bin_kernel(const int* __restrict__ src,
                           const int* __restrict__ dst, int E) {
    int e = blockIdx.x * blockDim.x + threadIdx.x;
    if (e >= E) {
        cudaGridDependencySynchronize();
        return;
    }
    int s = src[e];                            // independent of zero_kernel
    int d = dst[e];
    cudaGridDependencySynchronize();           // wait: zero_kernel complete
    atomicAdd(&g_outdeg[s], 1);                // result unused -> RED
    int slot = atomicAdd(&g_cursor[d], 1);
    if (slot < CAP) {
        g_bucket[d * CAP + slot] = s;
    } else {
        int pos = atomicAdd(&g_ovf_count, 1);
        if (pos < OVF_MAX) {
            g_ovf_src[pos] = s;
            g_ovf_dst[pos] = d;
        }
    }
}

// One thread computes 4 nodes' norms (vectorized int4 loads, float4 stores).
__global__ void norm_kernel(int n4) {
    int i = blockIdx.x * blockDim.x + threadIdx.x;
    cudaGridDependencySynchronize();           // wait: bin_kernel complete
    if (i >= n4) return;
    int4 od = ((const int4*)g_outdeg)[i];
    int4 id = ((const int4*)g_cursor)[i];
    float4 ns, nd;
    ns.x = rsqrtf((float)max(od.x, 1));
    ns.y = rsqrtf((float)max(od.y, 1));
    ns.z = rsqrtf((float)max(od.z, 1));
    ns.w = rsqrtf((float)max(od.w, 1));
    nd.x = rsqrtf((float)max(id.x, 1));
    nd.y = rsqrtf((float)max(id.y, 1));
    nd.z = rsqrtf((float)max(id.z, 1));
    nd.w = rsqrtf((float)max(id.w, 1));
    ((float4*)g_nsrc)[i] = ns;
    ((float4*)g_ndst)[i] = nd;
}

// Body verbatim: 16 lanes per node; lane q owns float4 #q.
__global__ void gather_kernel(const float4* __restrict__ feat,
                              float4* __restrict__ out, int N) {
    int t = blockIdx.x * blockDim.x + threadIdx.x;
    int node = t >> 4;
    int q = t & 15;
    cudaGridDependencySynchronize();           // wait: norm_kernel complete
    if (node >= N) return;

    int deg = __ldg(&g_cursor[node]);          // broadcast across the 16 lanes
    int k = min(deg, CAP);

    float4 acc = make_float4(0.f, 0.f, 0.f, 0.f);
    const int* bkt = &g_bucket[node * CAP];

    #pragma unroll 4
    for (int i = 0; i < k; i++) {
        int s = __ldg(&bkt[i]);                // broadcast (single line per node)
        float rn = __ldg(&g_nsrc[s]);          // broadcast
        float4 v = __ldg(&feat[(long long)s * DVEC + q]);
        acc.x = fmaf(v.x, rn, acc.x);
        acc.y = fmaf(v.y, rn, acc.y);
        acc.z = fmaf(v.z, rn, acc.z);
        acc.w = fmaf(v.w, rn, acc.w);
    }

    // Slow path: edges that overflowed this node's bucket (expected: none).
    if (deg > CAP) {
        int ovfn = min(g_ovf_count, OVF_MAX);
        for (int j = 0; j < ovfn; j++) {
            if (g_ovf_dst[j] == node) {
                int s = g_ovf_src[j];
                float rn = __ldg(&g_nsrc[s]);
                float4 v = __ldg(&feat[(long long)s * DVEC + q]);
                acc.x = fmaf(v.x, rn, acc.x);
                acc.y = fmaf(v.y, rn, acc.y);
                acc.z = fmaf(v.z, rn, acc.z);
                acc.w = fmaf(v.w, rn, acc.w);
            }
        }
    }

    float nd = __ldg(&g_ndst[node]);
    acc.x *= nd; acc.y *= nd; acc.z *= nd; acc.w *= nd;
    out[(long long)node * DVEC + q] = acc;
}

static inline void launch_pdl(void* func, dim3 grid, dim3 block,
                              void** args) {
    cudaLaunchConfig_t cfg;
    memset(&cfg, 0, sizeof(cfg));
    cudaLaunchAttribute attr[1];
    attr[0].id = cudaLaunchAttributeProgrammaticStreamSerialization;
    attr[0].val.programmaticStreamSerializationAllowed = 1;
    cfg.gridDim = grid;
    cfg.blockDim = block;
    cfg.dynamicSmemBytes = 0;
    cfg.stream = 0;
    cfg.attrs = attr;
    cfg.numAttrs = 1;
    cudaLaunchKernelExC(&cfg, func, args);
}

extern "C" void kernel_launch(void* const* d_in, const int* in_sizes, int n_in,
                              void* d_out, int out_size) {
    const float4* feat = (const float4*)d_in[0];
    const int*    src  = (const int*)d_in[1];
    const int*    dst  = (const int*)d_in[2];
    float4*       out  = (float4*)d_out;

    int N = in_sizes[0] / DFEAT;   // 100000
    int E = in_sizes[1];           // 1000000
    int N4 = (N + 3) / 4;          // 25000

    // 1) zero scratch (vectorized) — plain launch, head of the chain
    {
        int threads = 256;
        int blocks = (N4 + threads - 1) / threads;
        zero_kernel<<<blocks, threads>>>(N4);
    }

    // 2) degree count + dst binning — PDL on zero
    {
        int threads = 256;
        int blocks = (E + threads - 1) / threads;
        void* args[] = {(void*)&src, (void*)&dst, (void*)&E};
        launch_pdl((void*)bin_kernel, dim3(blocks), dim3(threads), args);
    }

    // 3) per-node norms — PDL on bin
    {
        int threads = 256;
        int blocks = (N4 + threads - 1) / threads;
        void* args[] = {(void*)&N4};
        launch_pdl((void*)norm_kernel, dim3(blocks), dim3(threads), args);
    }

    // 4) register-accumulated gather — PDL on norm (block 128)
    {
        long long total = (long long)N * DVEC;
        int threads = 128;
        int blocks = (int)((total + threads - 1) / threads);
        void* args[] = {(void*)&feat, (void*)&out, (void*)&N};
        launch_pdl((void*)gather_kernel, dim3(blocks), dim3(threads), args);
    }
}